// round 17
// baseline (speedup 1.0000x reference)
#include <cuda_runtime.h>
#include <cuda_fp16.h>
#include <stdint.h>

// ---------------------------------------------------------------------------
// RoadrunnerAttention (harness targets sm_103 -> mma.sync), R16:
//   R15 + attention re-partitioned to 4 warps x 32 rows (2 m16 row-blocks
//   per warp): halves the 8x-redundant K/V ldmatrix traffic per CTA.
// B=2, T=2048, H=1024, NH=16, DH=64, R=256, alpha=0.6
// ---------------------------------------------------------------------------

#define MROWS 4096
#define HDIM  1024
#define RDIM  256
#define R3T   (3 * RDIM)    // 768
#define H3T   (3 * HDIM)    // 3072
#define MH    (MROWS * HDIM)

// ---- device-global planes (no allocations allowed) ----
__device__ half g_xh [MROWS * HDIM];
__device__ half g_Ph [MROWS * R3T];
__device__ half g_QKVh[3 * MH];                        // Q | K | V (row blocks)
__device__ half g_Fh [MROWS * H3T];                    // Qf|Kf|Vf (col blocks)
__device__ half g_ch [MROWS * HDIM];
__device__ half g_cfh[MROWS * HDIM];
__device__ half g_Po [MROWS * RDIM];
__device__ half g_Vhh[4 * HDIM * RDIM];                // [K=H][N=R] hi
__device__ half g_Uh [4 * HDIM * RDIM];                // [N=H][K=R] hi
__device__ half g_Wh [4 * HDIM * HDIM];                // [K=H][N=H] hi

struct Ptr4 { const float* p[4]; };
struct F4   { float v[4]; };

#define SOFT_SC (0.125f * 1.44269504f)   // 1/sqrt(64) * log2(e)

// ---------------------------------------------------------------------------
// helpers
// ---------------------------------------------------------------------------
__device__ __forceinline__ void mma16816(
    float& c0, float& c1, float& c2, float& c3,
    uint32_t a0, uint32_t a1, uint32_t a2, uint32_t a3,
    uint32_t b0, uint32_t b1)
{
    asm volatile(
        "mma.sync.aligned.m16n8k16.row.col.f32.f16.f16.f32 "
        "{%0,%1,%2,%3}, {%4,%5,%6,%7}, {%8,%9}, {%0,%1,%2,%3};"
        : "+f"(c0), "+f"(c1), "+f"(c2), "+f"(c3)
        : "r"(a0), "r"(a1), "r"(a2), "r"(a3), "r"(b0), "r"(b1));
}
__device__ __forceinline__ uint32_t packh(float e0, float e1) {
    __half2 t = __floats2half2_rn(e0, e1);
    return *reinterpret_cast<uint32_t*>(&t);
}
__device__ __forceinline__ float ex2(float x) {
    float r; asm("ex2.approx.f32 %0, %1;" : "=f"(r) : "f"(x)); return r;
}
__device__ __forceinline__ uint32_t h2ex2(uint32_t x) {
    uint32_t r; asm("ex2.approx.f16x2 %0, %1;" : "=r"(r) : "r"(x)); return r;
}
__device__ __forceinline__ void cpa16(uint32_t dst, const void* src) {
    asm volatile("cp.async.cg.shared.global [%0], [%1], 16;\n"
                 :: "r"(dst), "l"(src) : "memory");
}
__device__ __forceinline__ void cpcommit() {
    asm volatile("cp.async.commit_group;\n" ::: "memory");
}
__device__ __forceinline__ void cpwait0() {
    asm volatile("cp.async.wait_group 0;\n" ::: "memory");
}
__device__ __forceinline__ void cpwait1() {
    asm volatile("cp.async.wait_group 1;\n" ::: "memory");
}
__device__ __forceinline__ void ldm4(uint32_t& r0, uint32_t& r1,
                                     uint32_t& r2, uint32_t& r3, uint32_t a) {
    asm volatile("ldmatrix.sync.aligned.m8n8.x4.shared.b16 {%0,%1,%2,%3}, [%4];"
                 : "=r"(r0), "=r"(r1), "=r"(r2), "=r"(r3) : "r"(a));
}
__device__ __forceinline__ void ldm4t(uint32_t& r0, uint32_t& r1,
                                      uint32_t& r2, uint32_t& r3, uint32_t a) {
    asm volatile("ldmatrix.sync.aligned.m8n8.x4.trans.shared.b16 {%0,%1,%2,%3}, [%4];"
                 : "=r"(r0), "=r"(r1), "=r"(r2), "=r"(r3) : "r"(a));
}
__device__ __forceinline__ void ldm2t(uint32_t& r0, uint32_t& r1, uint32_t a) {
    asm volatile("ldmatrix.sync.aligned.m8n8.x2.trans.shared.b16 {%0,%1}, [%2];"
                 : "=r"(r0), "=r"(r1) : "r"(a));
}
// ---- mbarrier ----
__device__ __forceinline__ void mbar_init(uint32_t a, uint32_t cnt) {
    asm volatile("mbarrier.init.shared.b64 [%0], %1;" :: "r"(a), "r"(cnt) : "memory");
}
__device__ __forceinline__ void mbar_wait(uint32_t a, uint32_t ph) {
    asm volatile(
        "{\n\t.reg .pred P;\n\t"
        "W%=:\n\t"
        "mbarrier.try_wait.parity.acquire.cta.shared::cta.b64 P, [%0], %1;\n\t"
        "@!P bra W%=;\n\t}"
        :: "r"(a), "r"(ph) : "memory");
}
__device__ __forceinline__ void mbar_arrive(uint32_t a) {
    asm volatile("mbarrier.arrive.shared.b64 _, [%0];" :: "r"(a) : "memory");
}
__device__ __forceinline__ void cpa_arrive(uint32_t a) {
    asm volatile("cp.async.mbarrier.arrive.noinc.shared.b64 [%0];"
                 :: "r"(a) : "memory");
}

// ---------------------------------------------------------------------------
// grouped quantize: 13 segments, grid-stride, MLP=4
// ---------------------------------------------------------------------------
struct QSeg  { const float4* src; __half2* dst; int n4; };
struct QSegs { QSeg s[13]; };

__device__ __forceinline__ void qstore(__half2* dst, int i, float4 f) {
    dst[2*i]   = __floats2half2_rn(f.x, f.y);
    dst[2*i+1] = __floats2half2_rn(f.z, f.w);
}

__global__ void quant_all(QSegs q)
{
    QSeg s = q.s[blockIdx.z];
    const int st = gridDim.x * blockDim.x;
    int i = blockIdx.x * blockDim.x + threadIdx.x;
    for (; i + 3 * st < s.n4; i += 4 * st) {
        float4 f0 = s.src[i];
        float4 f1 = s.src[i + st];
        float4 f2 = s.src[i + 2 * st];
        float4 f3 = s.src[i + 3 * st];
        qstore(s.dst, i,          f0);
        qstore(s.dst, i + st,     f1);
        qstore(s.dst, i + 2 * st, f2);
        qstore(s.dst, i + 3 * st, f3);
    }
    for (; i < s.n4; i += st) qstore(s.dst, i, s.src[i]);
}

// ---------------------------------------------------------------------------
// GEMM tile constants
// ---------------------------------------------------------------------------
#define APL     10240
#define BPL_NT  10240
#define BPL_NN  8704
#define SM_NN   (3 * (APL + BPL_NN))   // 56832
#define SM_NT   (3 * (APL + BPL_NT))   // 61440

// ---------------------------------------------------------------------------
// flat-packed grouped NN GEMM (per-group descriptor incl. A pointer)
// ---------------------------------------------------------------------------
struct GG {
    const half* A; const half* B; half* Ch; float* Cf;
    const float* cs; const float* bias;
    int ldb, ldc; float alpha, beta, ps;
};
struct GL {
    GG g[6];
    unsigned char zm[32];
    unsigned char xo[32];
};

__global__ __launch_bounds__(256, 2) void gemm_grp(int K, int lda, GL gs)
{
    const int zi = gs.zm[blockIdx.x];
    const int bx = gs.xo[blockIdx.x];
    const GG gg = gs.g[zi];

    constexpr int STAGE = APL + BPL_NN;
    extern __shared__ char smc[];
    const uint32_t su = (uint32_t)__cvta_generic_to_shared(smc);

    const half* Ah = gg.A;
    const half* Bh = gg.B;
    const int ldb = gg.ldb, ldc = gg.ldc;

    const int tid = threadIdx.x;
    const int lane = tid & 31, warp = tid >> 5;
    const int g = lane >> 2, tg = lane & 3;
    const int wm = warp >> 2, wn = warp & 3;
    const int row0 = blockIdx.y * 128, col0 = bx * 128;

    const int lr  = lane & 7;
    const int l8  = (lane >> 3) & 1;
    const int l16 = (lane >> 4) & 1;
    const int k8  = (lane >> 3) & 1;

    auto load_stage = [&](int s, int k0) {
        uint32_t sb = su + s * STAGE;
#pragma unroll
        for (int i = 0; i < 2; i++) {
            int w = tid + i * 256;
            int r = w >> 2, off = w & 3;
            cpa16(sb + r * 80 + off * 16,
                  Ah + (size_t)(row0 + r) * lda + k0 + off * 8);
        }
        uint32_t bb = sb + APL;
#pragma unroll
        for (int i = 0; i < 2; i++) {
            int w = tid + i * 256;
            int r = w >> 4, c = w & 15;
            cpa16(bb + r * 272 + c * 16,
                  Bh + (size_t)(k0 + r) * ldb + col0 + c * 8);
        }
    };

    float acc[4][4][4] = {};
    const int KT = K >> 5;

    load_stage(0, 0); cpcommit();
    if (KT > 1) load_stage(1, 32);
    cpcommit();

    for (int kt = 0; kt < KT; kt++) {
        if (kt + 1 < KT) cpwait1(); else cpwait0();
        __syncthreads();
        if (kt + 2 < KT) { load_stage((kt + 2) % 3, (kt + 2) * 32); cpcommit(); }
        uint32_t sb = su + (kt % 3) * STAGE;

#pragma unroll
        for (int ks = 0; ks < 2; ks++) {
            uint32_t ah[4][4];
            const int colA = ks * 16 + l16 * 8;
#pragma unroll
            for (int im = 0; im < 4; im++) {
                int rowA = wm * 64 + im * 16 + lr + l8 * 8;
                ldm4(ah[im][0], ah[im][1], ah[im][2], ah[im][3],
                     sb + rowA * 80 + colA * 2);
            }
#pragma unroll
            for (int jn = 0; jn < 4; jn += 2) {
                const int n0 = wn * 32 + jn * 8;
                uint32_t b0a, b1a, b0b, b1b;
                ldm4t(b0a, b1a, b0b, b1b,
                      sb + APL + (ks * 16 + lr + k8 * 8) * 272
                               + (n0 + l16 * 8) * 2);
#pragma unroll
                for (int im = 0; im < 4; im++) {
                    float* c0 = acc[im][jn];
                    float* c1 = acc[im][jn + 1];
                    mma16816(c0[0],c0[1],c0[2],c0[3],
                             ah[im][0],ah[im][1],ah[im][2],ah[im][3], b0a,b1a);
                    mma16816(c1[0],c1[1],c1[2],c1[3],
                             ah[im][0],ah[im][1],ah[im][2],ah[im][3], b0b,b1b);
                }
            }
        }
    }

#pragma unroll
    for (int im = 0; im < 4; im++) {
        int row = row0 + wm * 64 + im * 16 + g;
#pragma unroll
        for (int jn = 0; jn < 4; jn++) {
            int col = col0 + wn * 32 + jn * 8 + tg * 2;
            float v0 = acc[im][jn][0], v1 = acc[im][jn][1];
            float v2 = acc[im][jn][2], v3 = acc[im][jn][3];
            if (gg.cs) {
                float s0 = gg.cs[col], s1 = gg.cs[col + 1];
                v0 *= s0; v1 *= s1; v2 *= s0; v3 *= s1;
            }
            if (gg.bias) {
                float b0 = gg.bias[col], b1 = gg.bias[col + 1];
                v0 += b0; v1 += b1; v2 += b0; v3 += b1;
            }
            size_t o0 = (size_t)row * ldc + col;
            size_t o1 = (size_t)(row + 8) * ldc + col;
            if (gg.Cf) {
                float r0v = gg.alpha * v0, r1v = gg.alpha * v1;
                float r2v = gg.alpha * v2, r3v = gg.alpha * v3;
                if (gg.beta != 0.0f) {
                    float2 c0 = *(float2*)&gg.Cf[o0];
                    float2 c1 = *(float2*)&gg.Cf[o1];
                    r0v += gg.beta * c0.x; r1v += gg.beta * c0.y;
                    r2v += gg.beta * c1.x; r3v += gg.beta * c1.y;
                }
                *(float2*)&gg.Cf[o0] = make_float2(r0v, r1v);
                *(float2*)&gg.Cf[o1] = make_float2(r2v, r3v);
            } else {
                v0 *= gg.ps; v1 *= gg.ps; v2 *= gg.ps; v3 *= gg.ps;
                *(uint32_t*)&gg.Ch[o0] = packh(v0, v1);
                *(uint32_t*)&gg.Ch[o1] = packh(v2, v3);
            }
        }
    }
}

// ---------------------------------------------------------------------------
// NT GEMM (templated; stage-2 QKV and Po@U^T)
// ---------------------------------------------------------------------------
template <int MODE>
__global__ __launch_bounds__(256, 2) void gemm_nt(
    const half* __restrict__ Ah, const half* __restrict__ Bh,
    half* __restrict__ Ch, float* __restrict__ Cf,
    int K, int lda, int ldb, int ldc,
    int az, int bz, int cz, Ptr4 biasz, F4 psz,
    float alpha, float beta)
{
    constexpr int STAGE = APL + BPL_NT;
    extern __shared__ char smc[];
    const uint32_t su = (uint32_t)__cvta_generic_to_shared(smc);

    const int z = blockIdx.z;
    Ah += (size_t)z * az;
    Bh += (size_t)z * bz;
    if (Ch) Ch += (size_t)z * cz;
    if (Cf) Cf += (size_t)z * cz;
    const float* bias = biasz.p[z];
    const float ps = psz.v[z];

    const int tid = threadIdx.x;
    const int lane = tid & 31, warp = tid >> 5;
    const int g = lane >> 2, tg = lane & 3;
    const int wm = warp >> 2, wn = warp & 3;
    const int row0 = blockIdx.y * 128, col0 = blockIdx.x * 128;

    const int lr  = lane & 7;
    const int l8  = (lane >> 3) & 1;
    const int l16 = (lane >> 4) & 1;
    const int k8  = (lane >> 3) & 1;

    auto load_stage = [&](int s, int k0) {
        uint32_t sb = su + s * STAGE;
#pragma unroll
        for (int i = 0; i < 2; i++) {
            int w = tid + i * 256;
            int r = w >> 2, off = w & 3;
            cpa16(sb + r * 80 + off * 16,
                  Ah + (size_t)(row0 + r) * lda + k0 + off * 8);
        }
        uint32_t bb = sb + APL;
#pragma unroll
        for (int i = 0; i < 2; i++) {
            int w = tid + i * 256;
            int r = w >> 2, off = w & 3;
            cpa16(bb + r * 80 + off * 16,
                  Bh + (size_t)(col0 + r) * ldb + k0 + off * 8);
        }
    };

    float acc[4][4][4] = {};
    const int KT = K >> 5;

    load_stage(0, 0); cpcommit();
    if (KT > 1) load_stage(1, 32);
    cpcommit();

    for (int kt = 0; kt < KT; kt++) {
        if (kt + 1 < KT) cpwait1(); else cpwait0();
        __syncthreads();
        if (kt + 2 < KT) { load_stage((kt + 2) % 3, (kt + 2) * 32); cpcommit(); }
        uint32_t sb = su + (kt % 3) * STAGE;

#pragma unroll
        for (int ks = 0; ks < 2; ks++) {
            uint32_t ah[4][4];
            const int colA = ks * 16 + l16 * 8;
#pragma unroll
            for (int im = 0; im < 4; im++) {
                int rowA = wm * 64 + im * 16 + lr + l8 * 8;
                ldm4(ah[im][0], ah[im][1], ah[im][2], ah[im][3],
                     sb + rowA * 80 + colA * 2);
            }
#pragma unroll
            for (int jn = 0; jn < 4; jn += 2) {
                const int n0 = wn * 32 + jn * 8;
                uint32_t b0a, b1a, b0b, b1b;
                ldm4(b0a, b1a, b0b, b1b,
                     sb + APL + (n0 + l16 * 8 + lr) * 80
                              + (ks * 16 + k8 * 8) * 2);
#pragma unroll
                for (int im = 0; im < 4; im++) {
                    float* c0 = acc[im][jn];
                    float* c1 = acc[im][jn + 1];
                    mma16816(c0[0],c0[1],c0[2],c0[3],
                             ah[im][0],ah[im][1],ah[im][2],ah[im][3], b0a,b1a);
                    mma16816(c1[0],c1[1],c1[2],c1[3],
                             ah[im][0],ah[im][1],ah[im][2],ah[im][3], b0b,b1b);
                }
            }
        }
    }

#pragma unroll
    for (int im = 0; im < 4; im++) {
        int row = row0 + wm * 64 + im * 16 + g;
#pragma unroll
        for (int jn = 0; jn < 4; jn++) {
            int col = col0 + wn * 32 + jn * 8 + tg * 2;
            float v0 = acc[im][jn][0], v1 = acc[im][jn][1];
            float v2 = acc[im][jn][2], v3 = acc[im][jn][3];
            if (bias) {
                float b0 = bias[col], b1 = bias[col + 1];
                v0 += b0; v1 += b1; v2 += b0; v3 += b1;
            }
            size_t o0 = (size_t)row * ldc + col;
            size_t o1 = (size_t)(row + 8) * ldc + col;
            if (MODE == 0) {
                v0 *= ps; v1 *= ps; v2 *= ps; v3 *= ps;
                *(uint32_t*)&Ch[o0] = packh(v0, v1);
                *(uint32_t*)&Ch[o1] = packh(v2, v3);
            } else {
                float r0v = alpha * v0, r1v = alpha * v1;
                float r2v = alpha * v2, r3v = alpha * v3;
                if (beta != 0.0f) {
                    float2 c0 = *(float2*)&Cf[o0];
                    float2 c1 = *(float2*)&Cf[o1];
                    r0v += beta * c0.x; r1v += beta * c0.y;
                    r2v += beta * c1.x; r3v += beta * c1.y;
                }
                *(float2*)&Cf[o0] = make_float2(r0v, r1v);
                *(float2*)&Cf[o1] = make_float2(r2v, r3v);
            }
        }
    }
}

// ---------------------------------------------------------------------------
// Flash attention (causal): 4 warps x 32 rows (2 m16 row-blocks/warp);
// Q pre-scaled; ex2.f16x2 softmax; row-sum via hoisted ones-fragment MMA;
// 4-slot mbarrier ring; per-row-block masked-tile skip.
// BM=128, BN=64, 128 threads.  grid=(16, 32, 2).
// ---------------------------------------------------------------------------
#define ATT_QPL   (128 * 144)          // 18432
#define ATT_KVPL  (64 * 144)           // 9216
#define ATT_KVOFF ATT_QPL
#define ATT_STAGE (2 * ATT_KVPL)       // 18432
#define ATT_MB    (ATT_QPL + 4 * ATT_STAGE)      // 92160
#define ATT_SMEM  (ATT_MB + 64)                  // 92224
#define MB_F      ATT_MB
#define MB_E      (ATT_MB + 32)

__global__ __launch_bounds__(128, 2) void attn_split(void)
{
    extern __shared__ char smc[];
    const uint32_t su = (uint32_t)__cvta_generic_to_shared(smc);

    const half *Qh_, *Kh_, *Vh_;
    half *Oh_;
    int str;
    if (blockIdx.z == 0) {
        Qh_ = g_QKVh; Kh_ = g_QKVh + MH; Vh_ = g_QKVh + 2 * MH;
        Oh_ = g_ch;  str = HDIM;
    } else {
        Qh_ = g_Fh; Kh_ = g_Fh + HDIM; Vh_ = g_Fh + 2 * HDIM;
        Oh_ = g_cfh; str = H3T;
    }

    const int qt = (int)gridDim.x - 1 - (int)blockIdx.x;
    const int bh = blockIdx.y;
    const int b  = bh >> 4, h = bh & 15;
    const int rowbase = b * 2048 + qt * 128;
    const int colbase = h * 64;
    const int ktmax = 2 * qt + 1;

    const int tid  = threadIdx.x;
    const int lane = tid & 31, warp = tid >> 5;   // warp 0..3, 32 rows each
    const int g = lane >> 2, tg = lane & 3;
    const int lr  = lane & 7;
    const int l8  = (lane >> 3) & 1;
    const int l16 = (lane >> 4) & 1;
    const int k8  = (lane >> 3) & 1;
    const int wrow = warp * 32;

    auto load_kv = [&](int s, int kt) {
        const int kb = b * 2048 + kt * 64;
        uint32_t base = su + ATT_KVOFF + s * ATT_STAGE;
#pragma unroll
        for (int i = 0; i < 8; i++) {
            int idx = tid + i * 128;
            int pl = idx >> 9;
            int w = idx & 511;
            int r = w >> 3, off = w & 7;
            const half* src = pl ? Vh_ : Kh_;
            cpa16(base + pl * ATT_KVPL + r * 144 + off * 16,
                  src + (size_t)(kb + r) * str + colbase + off * 8);
        }
    };

    if (tid < 8) {
        mbar_init(su + MB_F + (tid & 3) * 8 + (tid >> 2) * 32, 128);
    }
    if (tid < 64) {
        uint32_t a = su + ATT_KVOFF + ATT_KVPL + tid * 144 + 128;
        asm volatile("st.shared.v4.b32 [%0], {%1, %2, %3, %4};"
                     :: "r"(a), "r"(0x3C00u), "r"(0u), "r"(0u), "r"(0u)
                     : "memory");
    }
    __syncthreads();

    uint32_t o0, o1;
    ldm2t(o0, o1, su + ATT_KVOFF + ATT_KVPL + (k8 * 8 + lr) * 144 + 128);

#pragma unroll
    for (int i = 0; i < 8; i++) {
        int c = tid + i * 128;
        int r = c >> 3, off = c & 7;
        cpa16(su + r * 144 + off * 16,
              Qh_ + (size_t)(rowbase + r) * str + colbase + off * 8);
    }
    load_kv(0, 0);
    cpa_arrive(su + MB_F);
    load_kv(1, 1);
    cpa_arrive(su + MB_F + 8);

    uint32_t qf[2][4][4];
    float accO[2][9][4] = {};
    float mrow[2][2] = {{-1e30f, -1e30f}, {-1e30f, -1e30f}};

    for (int kt = 0; kt <= ktmax; kt++) {
        const int t = kt + 2;
        if (t <= ktmax) {
            const int s = t & 3;
            if (t >= 4) mbar_wait(su + MB_E + s * 8, ((t >> 2) - 1) & 1);
            load_kv(s, t);
            cpa_arrive(su + MB_F + s * 8);
        }
        const int cs = kt & 3;
        mbar_wait(su + MB_F + cs * 8, (kt >> 2) & 1);
        uint32_t kv = su + ATT_KVOFF + cs * ATT_STAGE;

        if (kt == 0) {
#pragma unroll
            for (int rb = 0; rb < 2; rb++) {
                const int rowQ = wrow + rb * 16 + lr + l8 * 8;
#pragma unroll
                for (int ks = 0; ks < 4; ks++)
                    ldm4(qf[rb][ks][0], qf[rb][ks][1],
                         qf[rb][ks][2], qf[rb][ks][3],
                         su + rowQ * 144 + (ks * 16 + l16 * 8) * 2);
            }
        }

        const int D = kt * 64 - qt * 128;

#pragma unroll
        for (int rb = 0; rb < 2; rb++) {
            const int rbase = wrow + rb * 16;
            if (D > rbase + 15) continue;      // fully masked row-block

            // ---- S = Q @ K^T ----
            float s[8][4] = {};
#pragma unroll
            for (int ks = 0; ks < 4; ks++) {
#pragma unroll
                for (int jn = 0; jn < 8; jn += 2) {
                    uint32_t b0a, b1a, b0b, b1b;
                    ldm4(b0a, b1a, b0b, b1b,
                         kv + (jn * 8 + l16 * 8 + lr) * 144
                            + (ks * 16 + k8 * 8) * 2);
                    mma16816(s[jn][0],s[jn][1],s[jn][2],s[jn][3],
                             qf[rb][ks][0],qf[rb][ks][1],
                             qf[rb][ks][2],qf[rb][ks][3], b0a,b1a);
                    mma16816(s[jn+1][0],s[jn+1][1],s[jn+1][2],s[jn+1][3],
                             qf[rb][ks][0],qf[rb][ks][1],
                             qf[rb][ks][2],qf[rb][ks][3], b0b,b1b);
                }
            }

            if (D + 63 > rbase) {
                int rl0 = rbase + g, rl1 = rl0 + 8;
#pragma unroll
                for (int j = 0; j < 8; j++) {
                    int cg = j * 8 + tg * 2;
                    if (D + cg     > rl0) s[j][0] = -1e30f;
                    if (D + cg + 1 > rl0) s[j][1] = -1e30f;
                    if (D + cg     > rl1) s[j][2] = -1e30f;
                    if (D + cg + 1 > rl1) s[j][3] = -1e30f;
                }
            }

            // ---- online max + rescale ----
#pragma unroll
            for (int r = 0; r < 2; r++) {
                const int off = r * 2;
                float mx = -1e30f;
#pragma unroll
                for (int j = 0; j < 8; j++)
                    mx = fmaxf(mx, fmaxf(s[j][off], s[j][off + 1]));
                mx = fmaxf(mx, __shfl_xor_sync(0xffffffffu, mx, 1));
                mx = fmaxf(mx, __shfl_xor_sync(0xffffffffu, mx, 2));
                float mn = fmaxf(mrow[rb][r], mx);
                float sc = ex2(mrow[rb][r] - mn);
                mrow[rb][r] = mn;
#pragma unroll
                for (int j = 0; j < 8; j++) {
                    s[j][off] -= mn; s[j][off + 1] -= mn;
                }
#pragma unroll
                for (int jd = 0; jd < 9; jd++) {
                    accO[rb][jd][off] *= sc; accO[rb][jd][off + 1] *= sc;
                }
            }

            // ---- O += P @ V ----
#pragma unroll
            for (int ks = 0; ks < 4; ks++) {
                const int j0 = ks * 2, j1 = ks * 2 + 1;
                uint32_t pa0 = h2ex2(packh(s[j0][0], s[j0][1]));
                uint32_t pa1 = h2ex2(packh(s[j0][2], s[j0][3]));
                uint32_t pa2 = h2ex2(packh(s[j1][0], s[j1][1]));
                uint32_t pa3 = h2ex2(packh(s[j1][2], s[j1][3]));
#pragma unroll
                for (int jd = 0; jd < 8; jd += 2) {
                    uint32_t v0a, v1a, v0b, v1b;
                    ldm4t(v0a, v1a, v0b, v1b,
                          kv + ATT_KVPL + (ks * 16 + k8 * 8 + lr) * 144
                                        + (jd + l16) * 16);
                    float* c0 = accO[rb][jd];
                    float* c1 = accO[rb][jd + 1];
                    mma16816(c0[0],c0[1],c0[2],c0[3], pa0,pa1,pa2,pa3, v0a,v1a);
                    mma16816(c1[0],c1[1],c1[2],c1[3], pa0,pa1,pa2,pa3, v0b,v1b);
                }
                float* c8 = accO[rb][8];
                mma16816(c8[0],c8[1],c8[2],c8[3], pa0,pa1,pa2,pa3, o0,o1);
            }
        }

        mbar_arrive(su + MB_E + cs * 8);
    }

#pragma unroll
    for (int rb = 0; rb < 2; rb++) {
        float l0 = __shfl_sync(0xffffffffu, accO[rb][8][0], lane & 28);
        float l1 = __shfl_sync(0xffffffffu, accO[rb][8][2], lane & 28);
        float inv0 = 1.0f / l0, inv1 = 1.0f / l1;
        int row = rowbase + wrow + rb * 16 + g;
#pragma unroll
        for (int jd = 0; jd < 8; jd++) {
            int col = colbase + jd * 8 + tg * 2;
            size_t p0 = (size_t)row * HDIM + col;
            size_t p1 = (size_t)(row + 8) * HDIM + col;
            *(uint32_t*)&Oh_[p0] =
                packh(accO[rb][jd][0] * inv0, accO[rb][jd][1] * inv0);
            *(uint32_t*)&Oh_[p1] =
                packh(accO[rb][jd][2] * inv1, accO[rb][jd][3] * inv1);
        }
    }
}

// ---------------------------------------------------------------------------
extern "C" void kernel_launch(void* const* d_in, const int* in_sizes, int n_in,
                              void* d_out, int out_size)
{
    (void)in_sizes; (void)n_in; (void)out_size;
    const float* x = (const float*)d_in[0];
    const float* Vh_w[4] = {(const float*)d_in[2],  (const float*)d_in[6],
                            (const float*)d_in[10], (const float*)d_in[14]};
    const float* S_w [4] = {(const float*)d_in[3],  (const float*)d_in[7],
                            (const float*)d_in[11], (const float*)d_in[15]};
    const float* U_w [4] = {(const float*)d_in[4],  (const float*)d_in[8],
                            (const float*)d_in[12], (const float*)d_in[16]};
    const float* b_w [4] = {(const float*)d_in[5],  (const float*)d_in[9],
                            (const float*)d_in[13], (const float*)d_in[17]};
    const float* W_w [4] = {(const float*)d_in[18], (const float*)d_in[20],
                            (const float*)d_in[22], (const float*)d_in[24]};
    const float* bf_w[4] = {(const float*)d_in[19], (const float*)d_in[21],
                            (const float*)d_in[23], (const float*)d_in[25]};
    float* out = (float*)d_out;

#define SYM(T, p, s) T* p; cudaGetSymbolAddress((void**)&p, s)
    SYM(half, xh, g_xh);
    SYM(half, Ph, g_Ph);
    SYM(half, QKVh, g_QKVh);
    SYM(half, Fh, g_Fh);
    SYM(half, ch, g_ch);   SYM(half, cfh, g_cfh);
    SYM(half, Po, g_Po);
    SYM(half, Vhh, g_Vhh);
    SYM(half, Uh, g_Uh);
    SYM(half, Wh, g_Wh);
#undef SYM

    cudaFuncSetAttribute(gemm_grp,  cudaFuncAttributeMaxDynamicSharedMemorySize, SM_NN);
    cudaFuncSetAttribute(gemm_nt<0>, cudaFuncAttributeMaxDynamicSharedMemorySize, SM_NT);
    cudaFuncSetAttribute(gemm_nt<1>, cudaFuncAttributeMaxDynamicSharedMemorySize, SM_NT);
    cudaFuncSetAttribute(attn_split, cudaFuncAttributeMaxDynamicSharedMemorySize, ATT_SMEM);

    const int M = MROWS, H = HDIM, R = RDIM;
    dim3 blk(256);

    // ---- one grouped quant launch (13 segments) ----
    QSegs qs;
    qs.s[0] = {(const float4*)x, (__half2*)xh, MH / 4};
    for (int i = 0; i < 4; i++) {
        qs.s[1 + i] = {(const float4*)Vh_w[i],
                       (__half2*)(Vhh + (size_t)i * H * R), H * R / 4};
        qs.s[5 + i] = {(const float4*)U_w[i],
                       (__half2*)(Uh + (size_t)i * H * R), H * R / 4};
        qs.s[9 + i] = {(const float4*)W_w[i],
                       (__half2*)(Wh + (size_t)i * H * H), H * H / 4};
    }
    quant_all<<<dim3(128, 1, 13), 256>>>(qs);

    // ---- grouped proj launch (flat-packed): stage-1 + full-rank ----
    GL proj = {};
    for (int i = 0; i < 3; i++) {
        proj.g[i]     = {xh, Vhh + (size_t)i * H * R, Ph + i * R, nullptr,
                         S_w[i], nullptr, R, R3T, 0.f, 0.f, 1.f};
        proj.g[3 + i] = {xh, Wh + (size_t)i * H * H, Fh + i * H, nullptr,
                         nullptr, bf_w[i], H, H3T, 0.f, 0.f,
                         (i == 0) ? SOFT_SC : 1.f};
    }
    {
        int n = 0;
        for (int i = 0; i < 3; i++)
            for (int xq = 0; xq < 2; xq++) { proj.zm[n] = i; proj.xo[n] = xq; n++; }
        for (int i = 0; i < 3; i++)
            for (int xq = 0; xq < 8; xq++) { proj.zm[n] = 3 + i; proj.xo[n] = xq; n++; }
        gemm_grp<<<dim3(n, M / 128), blk, SM_NN>>>(H, H, proj);
    }

    // ---- stage-2 low-rank (NT): QKV_z = P_z @ U_z^T + b_z ; Q scaled ----
    Ptr4 bzQKV = {{b_w[0], b_w[1], b_w[2], nullptr}};
    F4 psQKV = {{SOFT_SC, 1.f, 1.f, 1.f}};
    gemm_nt<0><<<dim3(H / 128, M / 128, 3), blk, SM_NT>>>(
        Ph, Uh, QKVh, nullptr,
        R, R3T, R, H, R, H * R, MH, bzQKV, psQKV, 1.f, 0.f);

    // ---- both attentions (128-thread CTAs) ----
    attn_split<<<dim3(16, 32, 2), dim3(128), ATT_SMEM>>>();

    // ---- merged out launch: Wo (f32 0.4, nx=8) + ch->Po (fp16 S_o, nx=2) ----
    GL outg = {};
    outg.g[0] = {cfh, Wh + (size_t)3 * H * H, nullptr, out,
                 nullptr, bf_w[3], H, H, 0.4f, 0.f, 1.f};
    outg.g[1] = {ch, Vhh + (size_t)3 * H * R, Po, nullptr,
                 S_w[3], nullptr, R, R, 0.f, 0.f, 1.f};
    {
        int n = 0;
        for (int xq = 0; xq < 8; xq++) { outg.zm[n] = 0; outg.xo[n] = xq; n++; }
        for (int xq = 0; xq < 2; xq++) { outg.zm[n] = 1; outg.xo[n] = xq; n++; }
        gemm_grp<<<dim3(n, M / 128), blk, SM_NN>>>(H, H, outg);
    }

    // ---- final: out += 0.6 * Po @ U_o^T + b_o ----
    Ptr4 bzUo = {{b_w[3], nullptr, nullptr, nullptr}};
    F4 psUo = {{1.f, 1.f, 1.f, 1.f}};
    gemm_nt<1><<<dim3(H / 128, M / 128), blk, SM_NT>>>(
        Po, Uh + (size_t)3 * H * R, nullptr, out,
        R, R, R, H, 0, 0, 0, bzUo, psUo, 0.6f, 1.f);
}